// round 10
// baseline (speedup 1.0000x reference)
#include <cuda_runtime.h>
#include <cuda_fp16.h>
#include <math.h>
#include <stdint.h>

// ---------------- problem constants ----------------
#define B_   32768
#define T_   7
#define EIN  60
#define DIN  36
#define U_   356
#define G_   1424          // 4*U
#define H1_  768
#define OUT_ 168
#define HS   360           // padded h width (halves)
#define XS   64            // padded x width
#define KAP  448           // fused K padded
#define DECS 2496          // padded dec row
#define NCKS (KAP / 32)

// ---------------- scratch (device globals) ----------------------------
__device__ __align__(16) __half g_h0 [(size_t)B_ * HS];
__device__ __align__(16) __half g_h1 [(size_t)B_ * HS];
__device__ __align__(16) float  g_c  [(size_t)B_ * U_];
__device__ __align__(16) __half g_dec[(size_t)B_ * DECS];
__device__ __align__(16) __half g_t1 [(size_t)B_ * H1_];
__device__ __align__(16) __half g_t2 [(size_t)B_ * H1_];
__device__ __align__(16) __half g_xe [(size_t)B_ * T_ * XS];
__device__ __align__(16) __half g_xd [(size_t)B_ * T_ * XS];
__device__ __align__(16) __half g_wfe[(size_t)G_ * KAP];
__device__ __align__(16) __half g_wfd[(size_t)G_ * KAP];
__device__ __align__(16) float  g_bpe[G_];
__device__ __align__(16) float  g_bpd[G_];
#define WT_MAP  0
#define WT_W1   (WT_MAP + 768*DECS)
#define WT_W2   (WT_W1  + 768*768)
#define WT_WO   (WT_W2  + 768*768)
#define WT_TOTAL (WT_WO + 168*768)
__device__ __align__(16) __half g_wT[WT_TOTAL];

// ==================== helpers ====================
__device__ __forceinline__ uint32_t smem_u32(const void* p) {
    uint32_t a;
    asm("{ .reg .u64 t; cvta.to.shared.u64 t, %1; cvt.u32.u64 %0, t; }"
        : "=r"(a) : "l"(p));
    return a;
}
__device__ __forceinline__ void cpa16(uint32_t dst, const void* src, uint32_t sz) {
    asm volatile("cp.async.cg.shared.global [%0], [%1], 16, %2;"
                 :: "r"(dst), "l"(src), "r"(sz));
}
__device__ __forceinline__ void cpa_commit() {
    asm volatile("cp.async.commit_group;" ::: "memory");
}
__device__ __forceinline__ void cpa_wait(int ahead) {
    if (ahead >= 1) asm volatile("cp.async.wait_group 1;" ::: "memory");
    else            asm volatile("cp.async.wait_group 0;" ::: "memory");
}
#define LDSM_X4(r0, r1, r2, r3, addr)                                          \
    asm volatile("ldmatrix.sync.aligned.m8n8.x4.shared.b16 {%0,%1,%2,%3}, [%4];" \
                 : "=r"(r0), "=r"(r1), "=r"(r2), "=r"(r3) : "r"(addr))
__device__ __forceinline__ void mma_f16(float c[4],
                                        uint32_t a0, uint32_t a1,
                                        uint32_t a2, uint32_t a3,
                                        uint32_t b0, uint32_t b1)
{
    asm volatile(
        "mma.sync.aligned.m16n8k16.row.col.f32.f16.f16.f32 "
        "{%0,%1,%2,%3}, {%4,%5,%6,%7}, {%8,%9}, {%0,%1,%2,%3};"
        : "+f"(c[0]), "+f"(c[1]), "+f"(c[2]), "+f"(c[3])
        : "r"(a0), "r"(a1), "r"(a2), "r"(a3), "r"(b0), "r"(b1));
}
__device__ __forceinline__ float htanh(float v) {
    float r;
    asm("tanh.approx.f32 %0, %1;" : "=f"(r) : "f"(v));
    return r;
}
__device__ __forceinline__ float hsig(float v) {
    return fmaf(htanh(v * 0.5f), 0.5f, 0.5f);
}
__device__ __forceinline__ void store2(__half* p, float x, float y) {
    *reinterpret_cast<__half2*>(p) = __floats2half2_rn(x, y);
}
__device__ __forceinline__ void store2(float* p, float x, float y) {
    *reinterpret_cast<float2*>(p) = make_float2(x, y);
}

// smem: A tile 128 rows x 20 words, B tile 256 rows x 20 words; 3 stages
#define ROWW    20
#define ATILE_W (128 * ROWW)              // 2560 words
#define BTILE_W (256 * ROWW)              // 5120 words
#define STG_W   (ATILE_W + BTILE_W)       // 7680 words
#define NSTG    3
#define DSMEM   (NSTG * STG_W * 4)        // 92160 B
#define ZSTR    260                       // epilogue z row stride (words)

// ==================== fused LSTM step (128x256 tile) ====================
template<int WRITE_DEC>
__global__ void __launch_bounds__(256)
lstm_step(const __half* __restrict__ hin,
          const __half* __restrict__ xin,
          const __half* __restrict__ Wf,
          const float* __restrict__ bperm,
          __half* __restrict__ hout, float* __restrict__ cst,
          __half* __restrict__ dec, int dec_off)
{
    extern __shared__ __align__(16) char dynsmem[];
    const uint32_t sb = smem_u32(dynsmem);

    const int tid  = threadIdx.x;
    const int lane = tid & 31;
    const int w    = tid >> 5;
    const int m0   = blockIdx.y * 128;
    const int n0   = blockIdx.x * 256;

    const int wm = (w >> 2) * 64;     // 0,64
    const int wn = (w & 3) * 64;      // 0,64,128,192
    const int g  = lane >> 2;
    const int q4 = lane & 3;

    const int rs = tid >> 2;          // 0..63
    const int kq = tid & 3;

    const int a_off = (wm + (lane & 15)) * ROWW + (lane >> 4) * 4;
    const int b_off = (wn + (lane >> 4) * 8 + (lane & 7)) * ROWW
                    + ((lane >> 3) & 1) * 4;

    float acc[4][8][4];
#pragma unroll
    for (int i = 0; i < 4; i++)
#pragma unroll
        for (int j = 0; j < 8; j++)
#pragma unroll
            for (int q = 0; q < 4; q++) acc[i][j][q] = 0.f;

    auto issue = [&](int c) {
        const int s  = c % NSTG;
        const int kh = c * 32 + kq * 8;
        const uint32_t base = sb + (uint32_t)(s * STG_W * 4);
#pragma unroll
        for (int rr = 0; rr < 2; rr++) {          // A: 128 rows
            const int r = rs + rr * 64;
            const uint32_t da = base + (uint32_t)(r * ROWW * 4 + kq * 16);
            const void* asrc;
            uint32_t asz = 16;
            if (kh < HS)            asrc = hin + (size_t)(m0 + r) * HS + kh;
            else if (kh < HS + XS)  asrc = xin + (size_t)(m0 + r) * (T_ * XS) + (kh - HS);
            else { asrc = hin; asz = 0; }
            cpa16(da, asrc, asz);
        }
        const uint32_t bb = base + ATILE_W * 4;
#pragma unroll
        for (int rr = 0; rr < 4; rr++) {          // B: 256 rows
            const int r = rs + rr * 64;
            const int n = n0 + r;
            const uint32_t db = bb + (uint32_t)(r * ROWW * 4 + kq * 16);
            const void* bsrc = (n < G_) ? (const void*)(Wf + (size_t)n * KAP + kh)
                                        : (const void*)Wf;
            cpa16(db, bsrc, (n < G_) ? 16u : 0u);
        }
        cpa_commit();
    };

    issue(0); issue(1);

    for (int c = 0; c < NCKS; c++) {
        cpa_wait((NCKS - 1 - c < 1) ? 0 : 1);
        __syncthreads();
        if (c + 2 < NCKS) issue(c + 2);

        const uint32_t abase = sb + (uint32_t)(((c % NSTG) * STG_W) * 4);
        const uint32_t bbase = abase + ATILE_W * 4;
#pragma unroll
        for (int kg = 0; kg < 2; kg++) {
            const int kb = kg * 8;
            uint32_t af[4][4], bf[8][2];
#pragma unroll
            for (int mt = 0; mt < 4; mt++)
                LDSM_X4(af[mt][0], af[mt][1], af[mt][2], af[mt][3],
                        abase + (uint32_t)((a_off + mt * 16 * ROWW + kb) * 4));
#pragma unroll
            for (int p = 0; p < 4; p++)
                LDSM_X4(bf[2*p][0], bf[2*p][1], bf[2*p+1][0], bf[2*p+1][1],
                        bbase + (uint32_t)((b_off + p * 16 * ROWW + kb) * 4));
#pragma unroll
            for (int mt = 0; mt < 4; mt++)
#pragma unroll
                for (int nt = 0; nt < 8; nt++)
                    mma_f16(acc[mt][nt],
                            af[mt][0], af[mt][1], af[mt][2], af[mt][3],
                            bf[nt][0], bf[nt][1]);
        }
    }
    __syncthreads();

    // ---- epilogue: z -> smem (64-row halves) -> LSTM cell ----
    float* zs = (float*)dynsmem;      // 64 x ZSTR floats
    const int ubase = n0 >> 2;        // blockIdx.x * 64
    const int ul = tid & 63;
    const int rb = tid >> 6;          // 0..3
    const int unit = ubase + ul;
#pragma unroll
    for (int half = 0; half < 2; half++) {
        if ((w >> 2) == half) {
#pragma unroll
            for (int mt = 0; mt < 4; mt++) {
#pragma unroll
                for (int nt = 0; nt < 8; nt++) {
                    const int cr = wn + nt * 8 + 2 * q4;
                    const int col = n0 + cr;
                    if (col >= G_) continue;
                    const float bx = bperm[col], by = bperm[col + 1];
                    const int rl = mt * 16 + g;
                    zs[rl * ZSTR + cr]           = acc[mt][nt][0] + bx;
                    zs[rl * ZSTR + cr + 1]       = acc[mt][nt][1] + by;
                    zs[(rl + 8) * ZSTR + cr]     = acc[mt][nt][2] + bx;
                    zs[(rl + 8) * ZSTR + cr + 1] = acc[mt][nt][3] + by;
                }
            }
        }
        __syncthreads();
        if (unit < U_) {
#pragma unroll
            for (int rr = 0; rr < 16; rr++) {
                const int rl = rr * 4 + rb;
                const int b = m0 + half * 64 + rl;
                const float4 zv =
                    *reinterpret_cast<const float4*>(&zs[rl * ZSTR + ul * 4]);
                const float iv = hsig(zv.x);
                const float fv = hsig(zv.y);
                const float gv = htanh(zv.z);
                const float ov = hsig(zv.w);
                const size_t ci = (size_t)b * U_ + unit;
                const float cn = fv * cst[ci] + iv * gv;
                const float hn = ov * htanh(cn);
                cst[ci] = cn;
                hout[(size_t)b * HS + unit] = __float2half_rn(hn);
                if (WRITE_DEC)
                    dec[(size_t)b * DECS + dec_off + unit] = __float2half_rn(hn);
            }
        }
        __syncthreads();
    }
}

// ==================== fp16 GEMM (head, 128x256 tile) ====================
template<int ACT, typename TO>
__global__ void __launch_bounds__(256)
hgemm(const __half* __restrict__ A, int lda,
      const __half* __restrict__ Bt, int ldb,
      TO* __restrict__ C, int ldc,
      const float* __restrict__ bias,
      int N, int K)
{
    extern __shared__ __align__(16) char dynsmem[];
    const uint32_t sb = smem_u32(dynsmem);

    const int tid  = threadIdx.x;
    const int lane = tid & 31;
    const int w    = tid >> 5;
    const int m0   = blockIdx.y * 128;
    const int n0   = blockIdx.x * 256;

    const int wm = (w >> 2) * 64;
    const int wn = (w & 3) * 64;
    const int g  = lane >> 2;
    const int q4 = lane & 3;

    const int rs = tid >> 2;
    const int kq = tid & 3;

    const int a_off = (wm + (lane & 15)) * ROWW + (lane >> 4) * 4;
    const int b_off = (wn + (lane >> 4) * 8 + (lane & 7)) * ROWW
                    + ((lane >> 3) & 1) * 4;

    float acc[4][8][4];
#pragma unroll
    for (int i = 0; i < 4; i++)
#pragma unroll
        for (int j = 0; j < 8; j++)
#pragma unroll
            for (int q = 0; q < 4; q++) acc[i][j][q] = 0.f;

    const int nck = K >> 5;

    auto issue = [&](int c) {
        const int s  = c % NSTG;
        const int kh = c * 32 + kq * 8;
        const uint32_t base = sb + (uint32_t)(s * STG_W * 4);
#pragma unroll
        for (int rr = 0; rr < 2; rr++) {
            const int r = rs + rr * 64;
            cpa16(base + (uint32_t)(r * ROWW * 4 + kq * 16),
                  A + (size_t)(m0 + r) * lda + kh, 16);
        }
        const uint32_t bb = base + ATILE_W * 4;
#pragma unroll
        for (int rr = 0; rr < 4; rr++) {
            const int r = rs + rr * 64;
            const int n = n0 + r;
            const void* bsrc = (n < N) ? (const void*)(Bt + (size_t)n * ldb + kh)
                                       : (const void*)Bt;
            cpa16(bb + (uint32_t)(r * ROWW * 4 + kq * 16), bsrc,
                  (n < N) ? 16u : 0u);
        }
        cpa_commit();
    };

    issue(0); issue(1);

    for (int c = 0; c < nck; c++) {
        cpa_wait((nck - 1 - c < 1) ? 0 : 1);
        __syncthreads();
        if (c + 2 < nck) issue(c + 2);

        const uint32_t abase = sb + (uint32_t)(((c % NSTG) * STG_W) * 4);
        const uint32_t bbase = abase + ATILE_W * 4;
#pragma unroll
        for (int kg = 0; kg < 2; kg++) {
            const int kb = kg * 8;
            uint32_t af[4][4], bf[8][2];
#pragma unroll
            for (int mt = 0; mt < 4; mt++)
                LDSM_X4(af[mt][0], af[mt][1], af[mt][2], af[mt][3],
                        abase + (uint32_t)((a_off + mt * 16 * ROWW + kb) * 4));
#pragma unroll
            for (int p = 0; p < 4; p++)
                LDSM_X4(bf[2*p][0], bf[2*p][1], bf[2*p+1][0], bf[2*p+1][1],
                        bbase + (uint32_t)((b_off + p * 16 * ROWW + kb) * 4));
#pragma unroll
            for (int mt = 0; mt < 4; mt++)
#pragma unroll
                for (int nt = 0; nt < 8; nt++)
                    mma_f16(acc[mt][nt],
                            af[mt][0], af[mt][1], af[mt][2], af[mt][3],
                            bf[nt][0], bf[nt][1]);
        }
    }

#pragma unroll
    for (int mt = 0; mt < 4; mt++) {
#pragma unroll
        for (int nt = 0; nt < 8; nt++) {
            const int col = n0 + wn + nt * 8 + 2 * q4;
            if (col >= N) continue;
            const float bx = bias ? bias[col] : 0.f;
            const float by = bias ? bias[col + 1] : 0.f;
#pragma unroll
            for (int half = 0; half < 2; half++) {
                const int row = m0 + wm + mt * 16 + g + half * 8;
                float vx = acc[mt][nt][half * 2 + 0] + bx;
                float vy = acc[mt][nt][half * 2 + 1] + by;
                if (ACT == 1) { vx = fmaxf(vx, 0.f); vy = fmaxf(vy, 0.f); }
                if (ACT == 2) { vx = htanh(vx); vy = htanh(vy); }
                store2(&C[(size_t)row * ldc + col], vx, vy);
            }
        }
    }
}

// ==================== prep kernels (3 launches total) ====================
__global__ void cvt_both_kernel(const float* __restrict__ x,
                                const float* __restrict__ m,
                                __half* __restrict__ xe,
                                __half* __restrict__ xd)
{
    const int n = B_ * T_ * XS;
    const int i = blockIdx.x * 256 + threadIdx.x;
    if (i < n) {
        const int j = i & (XS - 1);
        const int bt = i >> 6;
        xe[i] = (j < EIN) ? __float2half_rn(x[(size_t)bt * EIN + j])
                          : __float2half_rn(0.f);
    } else if (i < 2 * n) {
        const int k = i - n;
        const int j = k & (XS - 1);
        const int bt = k >> 6;
        xd[k] = (j < DIN) ? __float2half_rn(m[(size_t)bt * DIN + j])
                          : __float2half_rn(0.f);
    }
}

__global__ void build_wf_both_kernel(const float* __restrict__ encR,
                                     const float* __restrict__ encK,
                                     const float* __restrict__ encB,
                                     const float* __restrict__ decR,
                                     const float* __restrict__ decK,
                                     const float* __restrict__ decB,
                                     __half* __restrict__ wfe,
                                     __half* __restrict__ wfd,
                                     float* __restrict__ bpe,
                                     float* __restrict__ bpd)
{
    const int j = blockIdx.y;
    const int k = blockIdx.x * 256 + threadIdx.x;
    if (k >= KAP) return;
    const int oj = (j & 3) * U_ + (j >> 2);
    const int isdec = blockIdx.z;
    const float* R   = isdec ? decR : encR;
    const float* Kin = isdec ? decK : encK;
    const float* bi  = isdec ? decB : encB;
    __half* wf = isdec ? wfd : wfe;
    float*  bp = isdec ? bpd : bpe;
    const int Kx = isdec ? DIN : EIN;
    float v = 0.f;
    if (k < U_)                      v = R[(size_t)k * G_ + oj];
    else if (k >= HS && k < HS + Kx) v = Kin[(size_t)(k - HS) * G_ + oj];
    wf[(size_t)j * KAP + k] = __float2half_rn(v);
    if (k == 0) bp[j] = bi[oj];
}

__global__ void transpose_h_kernel(const float* __restrict__ in,
                                   __half* __restrict__ out,
                                   int R, int Cc, int ldo)
{
    __shared__ float t[32][33];
    const int c0 = blockIdx.x * 32, r0 = blockIdx.y * 32;
    const int x = threadIdx.x, y = threadIdx.y;
#pragma unroll
    for (int dy = 0; dy < 32; dy += 8) {
        const int r = r0 + y + dy, c = c0 + x;
        t[y + dy][x] = (r < R && c < Cc) ? in[(size_t)r * Cc + c] : 0.f;
    }
    __syncthreads();
#pragma unroll
    for (int dy = 0; dy < 32; dy += 8) {
        const int r = c0 + y + dy, c = r0 + x;
        if (r < Cc && c < ldo)
            out[(size_t)r * ldo + c] = __float2half_rn(c < R ? t[x][y + dy] : 0.f);
    }
}

__global__ void zero_hc_kernel(__half* h, float* c)
{
    const int i = blockIdx.x * 256 + threadIdx.x;
    if (i < B_ * HS) h[i] = __float2half_rn(0.f);
    if (i < B_ * U_) c[i] = 0.f;
}

// ==================== host orchestration ====================
extern "C" void kernel_launch(void* const* d_in, const int* in_sizes, int n_in,
                              void* d_out, int out_size)
{
    const float* x    = (const float*)d_in[0];
    const float* m    = (const float*)d_in[1];
    const float* encK = (const float*)d_in[2];
    const float* encR = (const float*)d_in[3];
    const float* encB = (const float*)d_in[4];
    const float* decK = (const float*)d_in[5];
    const float* decR = (const float*)d_in[6];
    const float* decB = (const float*)d_in[7];
    const float* Wmap = (const float*)d_in[8];
    const float* bmap = (const float*)d_in[9];
    const float* W1   = (const float*)d_in[10];
    const float* b1   = (const float*)d_in[11];
    const float* W2   = (const float*)d_in[12];
    const float* b2   = (const float*)d_in[13];
    const float* Wo   = (const float*)d_in[14];
    const float* bo   = (const float*)d_in[15];
    float* out = (float*)d_out;

    __half *h0, *h1, *dec, *t1, *t2, *xe, *xd, *wfe, *wfd, *wT;
    float *c, *bpe, *bpd;
    cudaGetSymbolAddress((void**)&h0,  g_h0);
    cudaGetSymbolAddress((void**)&h1,  g_h1);
    cudaGetSymbolAddress((void**)&c,   g_c);
    cudaGetSymbolAddress((void**)&dec, g_dec);
    cudaGetSymbolAddress((void**)&t1,  g_t1);
    cudaGetSymbolAddress((void**)&t2,  g_t2);
    cudaGetSymbolAddress((void**)&xe,  g_xe);
    cudaGetSymbolAddress((void**)&xd,  g_xd);
    cudaGetSymbolAddress((void**)&wfe, g_wfe);
    cudaGetSymbolAddress((void**)&wfd, g_wfd);
    cudaGetSymbolAddress((void**)&bpe, g_bpe);
    cudaGetSymbolAddress((void**)&bpd, g_bpd);
    cudaGetSymbolAddress((void**)&wT,  g_wT);

    cudaFuncSetAttribute(lstm_step<0>, cudaFuncAttributeMaxDynamicSharedMemorySize, DSMEM);
    cudaFuncSetAttribute(lstm_step<1>, cudaFuncAttributeMaxDynamicSharedMemorySize, DSMEM);
    cudaFuncSetAttribute(hgemm<1, __half>, cudaFuncAttributeMaxDynamicSharedMemorySize, DSMEM);
    cudaFuncSetAttribute(hgemm<2, __half>, cudaFuncAttributeMaxDynamicSharedMemorySize, DSMEM);
    cudaFuncSetAttribute(hgemm<0, float>,  cudaFuncAttributeMaxDynamicSharedMemorySize, DSMEM);

    // ---- prep: exactly 3 launches, so first lstm_step = stream launch #3 ----
    {
        const int n2 = 2 * B_ * T_ * XS;
        cvt_both_kernel<<<(n2 + 255) / 256, 256>>>(x, m, xe, xd);          // 0
    }
    build_wf_both_kernel<<<dim3((KAP + 255) / 256, G_, 2), 256>>>(
        encR, encK, encB, decR, decK, decB, wfe, wfd, bpe, bpd);           // 1
    {
        const int n = B_ * HS;
        zero_hc_kernel<<<(n + 255) / 256, 256>>>(h0, c);                   // 2
    }

    const dim3 grS((G_ + 255) / 256, B_ / 128);   // (6, 256)
    __half* hc = h0;
    __half* hn = h1;

    // encoder
    for (int t = 0; t < T_; t++) {
        lstm_step<0><<<grS, 256, DSMEM>>>(hc, xe + t * XS, wfe, bpe,
                                          hn, c, (__half*)nullptr, 0);
        __half* tmp = hc; hc = hn; hn = tmp;
    }
    // decoder
    for (int t = 0; t < T_; t++) {
        lstm_step<1><<<grS, 256, DSMEM>>>(hc, xd + t * XS, wfd, bpd,
                                          hn, c, dec, t * U_);
        __half* tmp = hc; hc = hn; hn = tmp;
    }

    // head weight transposes
    {
        dim3 tb(32, 8);
        transpose_h_kernel<<<dim3((H1_+31)/32, (DECS+31)/32), tb>>>(Wmap, wT+WT_MAP, T_*U_, H1_, DECS);
        transpose_h_kernel<<<dim3((H1_+31)/32, (H1_+31)/32),  tb>>>(W1, wT+WT_W1, H1_, H1_, H1_);
        transpose_h_kernel<<<dim3((H1_+31)/32, (H1_+31)/32),  tb>>>(W2, wT+WT_W2, H1_, H1_, H1_);
        transpose_h_kernel<<<dim3((OUT_+31)/32, (H1_+31)/32), tb>>>(Wo, wT+WT_WO, H1_, OUT_, H1_);
    }

    // dense head
    const dim3 grH((H1_ + 255) / 256, B_ / 128);   // (3, 256)
    const dim3 grO((OUT_ + 255) / 256, B_ / 128);  // (1, 256)
    hgemm<1, __half><<<grH, 256, DSMEM>>>(dec, DECS, wT + WT_MAP, DECS,
                                          t1, H1_, bmap, H1_, DECS);
    hgemm<2, __half><<<grH, 256, DSMEM>>>(t1, H1_, wT + WT_W1, H1_,
                                          t2, H1_, b1, H1_, H1_);
    hgemm<2, __half><<<grH, 256, DSMEM>>>(t2, H1_, wT + WT_W2, H1_,
                                          t1, H1_, b2, H1_, H1_);
    hgemm<0, float><<<grO, 256, DSMEM>>>(t1, H1_, wT + WT_WO, H1_,
                                         out, OUT_, bo, OUT_, H1_);
}

// round 11
// speedup vs baseline: 1.4449x; 1.4449x over previous
#include <cuda_runtime.h>
#include <cuda_fp16.h>
#include <math.h>
#include <stdint.h>

// ---------------- problem constants ----------------
#define B_   32768
#define T_   7
#define EIN  60
#define DIN  36
#define U_   356
#define G_   1424          // 4*U
#define H1_  768
#define OUT_ 168
#define HS   360           // padded h width (halves)
#define XS   64            // padded x width
#define KAP  448           // fused K padded
#define DECS 2496          // padded dec row
#define NCKS (KAP / 32)

// ---------------- scratch (device globals) ----------------------------
__device__ __align__(16) __half g_h0 [(size_t)B_ * HS];
__device__ __align__(16) __half g_h1 [(size_t)B_ * HS];
__device__ __align__(16) float  g_c  [(size_t)B_ * U_];
__device__ __align__(16) __half g_dec[(size_t)B_ * DECS];
__device__ __align__(16) __half g_t1 [(size_t)B_ * H1_];
__device__ __align__(16) __half g_t2 [(size_t)B_ * H1_];
__device__ __align__(16) __half g_xe [(size_t)B_ * T_ * XS];
__device__ __align__(16) __half g_xd [(size_t)B_ * T_ * XS];
__device__ __align__(16) __half g_wfe[(size_t)G_ * KAP];
__device__ __align__(16) __half g_wfd[(size_t)G_ * KAP];
__device__ __align__(16) float  g_bpe[G_];
__device__ __align__(16) float  g_bpd[G_];
#define WT_MAP  0
#define WT_W1   (WT_MAP + 768*DECS)
#define WT_W2   (WT_W1  + 768*768)
#define WT_WO   (WT_W2  + 768*768)
#define WT_TOTAL (WT_WO + 168*768)
__device__ __align__(16) __half g_wT[WT_TOTAL];

// ==================== helpers ====================
__device__ __forceinline__ uint32_t smem_u32(const void* p) {
    uint32_t a;
    asm("{ .reg .u64 t; cvta.to.shared.u64 t, %1; cvt.u32.u64 %0, t; }"
        : "=r"(a) : "l"(p));
    return a;
}
__device__ __forceinline__ void cpa16(uint32_t dst, const void* src, uint32_t sz) {
    asm volatile("cp.async.cg.shared.global [%0], [%1], 16, %2;"
                 :: "r"(dst), "l"(src), "r"(sz));
}
__device__ __forceinline__ void cpa_commit() {
    asm volatile("cp.async.commit_group;" ::: "memory");
}
__device__ __forceinline__ void cpa_wait(int ahead) {
    if (ahead >= 2)      asm volatile("cp.async.wait_group 2;" ::: "memory");
    else if (ahead == 1) asm volatile("cp.async.wait_group 1;" ::: "memory");
    else                 asm volatile("cp.async.wait_group 0;" ::: "memory");
}
#define LDSM_X4(r0, r1, r2, r3, addr)                                          \
    asm volatile("ldmatrix.sync.aligned.m8n8.x4.shared.b16 {%0,%1,%2,%3}, [%4];" \
                 : "=r"(r0), "=r"(r1), "=r"(r2), "=r"(r3) : "r"(addr))
__device__ __forceinline__ void mma_f16(float c[4],
                                        uint32_t a0, uint32_t a1,
                                        uint32_t a2, uint32_t a3,
                                        uint32_t b0, uint32_t b1)
{
    asm volatile(
        "mma.sync.aligned.m16n8k16.row.col.f32.f16.f16.f32 "
        "{%0,%1,%2,%3}, {%4,%5,%6,%7}, {%8,%9}, {%0,%1,%2,%3};"
        : "+f"(c[0]), "+f"(c[1]), "+f"(c[2]), "+f"(c[3])
        : "r"(a0), "r"(a1), "r"(a2), "r"(a3), "r"(b0), "r"(b1));
}
__device__ __forceinline__ float htanh(float v) {
    float r;
    asm("tanh.approx.f32 %0, %1;" : "=f"(r) : "f"(v));
    return r;
}
__device__ __forceinline__ float hsig(float v) {
    return fmaf(htanh(v * 0.5f), 0.5f, 0.5f);
}
__device__ __forceinline__ void store2(__half* p, float x, float y) {
    *reinterpret_cast<__half2*>(p) = __floats2half2_rn(x, y);
}
__device__ __forceinline__ void store2(float* p, float x, float y) {
    *reinterpret_cast<float2*>(p) = make_float2(x, y);
}

// smem tile: 128 rows x 20 words (32 halves used + 8 pad), per operand
#define ROWW   20
#define TILE_W (128 * ROWW)          // words
#define STG_W  (2 * TILE_W)          // A+B per stage, words
#define NSTG   4
#define DSMEM  (NSTG * STG_W * 4)    // 81920 B  (x2 CTAs = 160KB < 228KB/SM)

// ==================== fused LSTM step (fp16, 128x128, 2 CTAs/SM) ==========
template<int WRITE_DEC>
__global__ void __launch_bounds__(256, 2)
lstm_step(const __half* __restrict__ hin,
          const __half* __restrict__ xin,       // + t*XS, stride T_*XS
          const __half* __restrict__ Wf,
          const float* __restrict__ bperm,
          __half* __restrict__ hout, float* __restrict__ cst,
          __half* __restrict__ dec, int dec_off)
{
    extern __shared__ __align__(16) char dynsmem[];
    const uint32_t sb = smem_u32(dynsmem);

    const int tid  = threadIdx.x;
    const int lane = tid & 31;
    const int w    = tid >> 5;
    const int m0   = blockIdx.y * 128;
    const int n0   = blockIdx.x * 128;

    const int wm = (w >> 2) * 64;
    const int wn = (w & 3) * 32;
    const int g  = lane >> 2;
    const int q4 = lane & 3;

    const int rs = tid >> 2;
    const int kq = tid & 3;

    const int a_off = (wm + (lane & 15)) * ROWW + (lane >> 4) * 4;
    const int b_off = (wn + (lane >> 4) * 8 + (lane & 7)) * ROWW
                    + ((lane >> 3) & 1) * 4;

    float acc[4][4][4];
#pragma unroll
    for (int i = 0; i < 4; i++)
#pragma unroll
        for (int j = 0; j < 4; j++)
#pragma unroll
            for (int q = 0; q < 4; q++) acc[i][j][q] = 0.f;

    auto issue = [&](int c) {
        const int s  = c & 3;
        const int kh = c * 32 + kq * 8;
        const uint32_t base = sb + (uint32_t)(s * STG_W * 4);
#pragma unroll
        for (int rr = 0; rr < 2; rr++) {
            const int r = rs + rr * 64;
            const uint32_t da = base + (uint32_t)(r * ROWW * 4 + kq * 16);
            const void* asrc;
            uint32_t asz = 16;
            if (kh < HS)            asrc = hin + (size_t)(m0 + r) * HS + kh;
            else if (kh < HS + XS)  asrc = xin + (size_t)(m0 + r) * (T_ * XS) + (kh - HS);
            else { asrc = hin; asz = 0; }
            cpa16(da, asrc, asz);
            const int n = n0 + r;
            const void* bsrc = (n < G_) ? (const void*)(Wf + (size_t)n * KAP + kh)
                                        : (const void*)Wf;
            cpa16(da + TILE_W * 4, bsrc, (n < G_) ? 16u : 0u);
        }
        cpa_commit();
    };

    issue(0); issue(1); issue(2);

    for (int c = 0; c < NCKS; c++) {
        const int last = (NCKS - 1 < c + 2) ? NCKS - 1 : c + 2;
        cpa_wait(last - c);
        __syncthreads();
        if (c + 3 < NCKS) issue(c + 3);

        const uint32_t abase = sb + (uint32_t)(((c & 3) * STG_W) * 4);
        const uint32_t bbase = abase + TILE_W * 4;
#pragma unroll
        for (int kg = 0; kg < 2; kg++) {
            const int kb = kg * 8;
            uint32_t af[4][4], bf[4][2];
#pragma unroll
            for (int mt = 0; mt < 4; mt++)
                LDSM_X4(af[mt][0], af[mt][1], af[mt][2], af[mt][3],
                        abase + (uint32_t)((a_off + mt * 16 * ROWW + kb) * 4));
#pragma unroll
            for (int p = 0; p < 2; p++)
                LDSM_X4(bf[2*p][0], bf[2*p][1], bf[2*p+1][0], bf[2*p+1][1],
                        bbase + (uint32_t)((b_off + p * 16 * ROWW + kb) * 4));
#pragma unroll
            for (int mt = 0; mt < 4; mt++)
#pragma unroll
                for (int nt = 0; nt < 4; nt++)
                    mma_f16(acc[mt][nt],
                            af[mt][0], af[mt][1], af[mt][2], af[mt][3],
                            bf[nt][0], bf[nt][1]);
        }
    }
    __syncthreads();   // protect smem reuse by epilogue overlay

    // ---- epilogue: z -> smem (64-row halves) -> LSTM cell ----
    float* zs = (float*)dynsmem;
    const int ubase = n0 >> 2;
    const int ul = tid & 31;
    const int rb = tid >> 5;
    const int unit = ubase + ul;
#pragma unroll
    for (int half = 0; half < 2; half++) {
        if ((w >> 2) == half) {
#pragma unroll
            for (int mt = 0; mt < 4; mt++) {
#pragma unroll
                for (int nt = 0; nt < 4; nt++) {
                    const int col = n0 + wn + nt * 8 + 2 * q4;
                    if (col >= G_) continue;
                    const float bx = bperm[col], by = bperm[col + 1];
                    const int cr = wn + nt * 8 + 2 * q4;
                    const int rl = mt * 16 + g;
                    zs[rl * 132 + cr]           = acc[mt][nt][0] + bx;
                    zs[rl * 132 + cr + 1]       = acc[mt][nt][1] + by;
                    zs[(rl + 8) * 132 + cr]     = acc[mt][nt][2] + bx;
                    zs[(rl + 8) * 132 + cr + 1] = acc[mt][nt][3] + by;
                }
            }
        }
        __syncthreads();
        if (unit < U_) {
#pragma unroll
            for (int rr = 0; rr < 8; rr++) {
                const int rl = rr * 8 + rb;
                const int b = m0 + half * 64 + rl;
                const float4 zv =
                    *reinterpret_cast<const float4*>(&zs[rl * 132 + ul * 4]);
                const float iv = hsig(zv.x);
                const float fv = hsig(zv.y);
                const float gv = htanh(zv.z);
                const float ov = hsig(zv.w);
                const size_t ci = (size_t)b * U_ + unit;
                const float cn = fv * cst[ci] + iv * gv;
                const float hn = ov * htanh(cn);
                cst[ci] = cn;
                hout[(size_t)b * HS + unit] = __float2half_rn(hn);
                if (WRITE_DEC)
                    dec[(size_t)b * DECS + dec_off + unit] = __float2half_rn(hn);
            }
        }
        __syncthreads();
    }
}

// ==================== fp16 GEMM (head, 128x128, 2 CTAs/SM) ====================
template<int ACT, typename TO> // ACT: 0 none, 1 relu, 2 tanh
__global__ void __launch_bounds__(256, 2)
hgemm(const __half* __restrict__ A, int lda,
      const __half* __restrict__ Bt, int ldb,
      TO* __restrict__ C, int ldc,
      const float* __restrict__ bias,
      int N, int K)
{
    extern __shared__ __align__(16) char dynsmem[];
    const uint32_t sb = smem_u32(dynsmem);

    const int tid  = threadIdx.x;
    const int lane = tid & 31;
    const int w    = tid >> 5;
    const int m0   = blockIdx.y * 128;
    const int n0   = blockIdx.x * 128;

    const int wm = (w >> 2) * 64;
    const int wn = (w & 3) * 32;
    const int g  = lane >> 2;
    const int q4 = lane & 3;

    const int rs = tid >> 2;
    const int kq = tid & 3;

    const int a_off = (wm + (lane & 15)) * ROWW + (lane >> 4) * 4;
    const int b_off = (wn + (lane >> 4) * 8 + (lane & 7)) * ROWW
                    + ((lane >> 3) & 1) * 4;

    float acc[4][4][4];
#pragma unroll
    for (int i = 0; i < 4; i++)
#pragma unroll
        for (int j = 0; j < 4; j++)
#pragma unroll
            for (int q = 0; q < 4; q++) acc[i][j][q] = 0.f;

    const int nck = K >> 5;

    auto issue = [&](int c) {
        const int s  = c & 3;
        const int kh = c * 32 + kq * 8;
        const uint32_t base = sb + (uint32_t)(s * STG_W * 4);
#pragma unroll
        for (int rr = 0; rr < 2; rr++) {
            const int r = rs + rr * 64;
            const uint32_t da = base + (uint32_t)(r * ROWW * 4 + kq * 16);
            cpa16(da, A + (size_t)(m0 + r) * lda + kh, 16);
            const int n = n0 + r;
            const void* bsrc = (n < N) ? (const void*)(Bt + (size_t)n * ldb + kh)
                                       : (const void*)Bt;
            cpa16(da + TILE_W * 4, bsrc, (n < N) ? 16u : 0u);
        }
        cpa_commit();
    };

    issue(0); issue(1); issue(2);

    for (int c = 0; c < nck; c++) {
        const int last = (nck - 1 < c + 2) ? nck - 1 : c + 2;
        cpa_wait(last - c);
        __syncthreads();
        if (c + 3 < nck) issue(c + 3);

        const uint32_t abase = sb + (uint32_t)(((c & 3) * STG_W) * 4);
        const uint32_t bbase = abase + TILE_W * 4;
#pragma unroll
        for (int kg = 0; kg < 2; kg++) {
            const int kb = kg * 8;
            uint32_t af[4][4], bf[4][2];
#pragma unroll
            for (int mt = 0; mt < 4; mt++)
                LDSM_X4(af[mt][0], af[mt][1], af[mt][2], af[mt][3],
                        abase + (uint32_t)((a_off + mt * 16 * ROWW + kb) * 4));
#pragma unroll
            for (int p = 0; p < 2; p++)
                LDSM_X4(bf[2*p][0], bf[2*p][1], bf[2*p+1][0], bf[2*p+1][1],
                        bbase + (uint32_t)((b_off + p * 16 * ROWW + kb) * 4));
#pragma unroll
            for (int mt = 0; mt < 4; mt++)
#pragma unroll
                for (int nt = 0; nt < 4; nt++)
                    mma_f16(acc[mt][nt],
                            af[mt][0], af[mt][1], af[mt][2], af[mt][3],
                            bf[nt][0], bf[nt][1]);
        }
    }

#pragma unroll
    for (int mt = 0; mt < 4; mt++) {
#pragma unroll
        for (int nt = 0; nt < 4; nt++) {
            const int col = n0 + wn + nt * 8 + 2 * q4;
            if (col >= N) continue;
            const float bx = bias ? bias[col] : 0.f;
            const float by = bias ? bias[col + 1] : 0.f;
#pragma unroll
            for (int half = 0; half < 2; half++) {
                const int row = m0 + wm + mt * 16 + g + half * 8;
                float vx = acc[mt][nt][half * 2 + 0] + bx;
                float vy = acc[mt][nt][half * 2 + 1] + by;
                if (ACT == 1) { vx = fmaxf(vx, 0.f); vy = fmaxf(vy, 0.f); }
                if (ACT == 2) { vx = htanh(vx); vy = htanh(vy); }
                store2(&C[(size_t)row * ldc + col], vx, vy);
            }
        }
    }
}

// ==================== prep kernels (3 launches total) ====================
__global__ void cvt_both_kernel(const float* __restrict__ x,
                                const float* __restrict__ m,
                                __half* __restrict__ xe,
                                __half* __restrict__ xd)
{
    const int n = B_ * T_ * XS;
    const int i = blockIdx.x * 256 + threadIdx.x;
    if (i < n) {
        const int j = i & (XS - 1);
        const int bt = i >> 6;
        xe[i] = (j < EIN) ? __float2half_rn(x[(size_t)bt * EIN + j])
                          : __float2half_rn(0.f);
    } else if (i < 2 * n) {
        const int k = i - n;
        const int j = k & (XS - 1);
        const int bt = k >> 6;
        xd[k] = (j < DIN) ? __float2half_rn(m[(size_t)bt * DIN + j])
                          : __float2half_rn(0.f);
    }
}

__global__ void build_wf_both_kernel(const float* __restrict__ encR,
                                     const float* __restrict__ encK,
                                     const float* __restrict__ encB,
                                     const float* __restrict__ decR,
                                     const float* __restrict__ decK,
                                     const float* __restrict__ decB,
                                     __half* __restrict__ wfe,
                                     __half* __restrict__ wfd,
                                     float* __restrict__ bpe,
                                     float* __restrict__ bpd)
{
    const int j = blockIdx.y;
    const int k = blockIdx.x * 256 + threadIdx.x;
    if (k >= KAP) return;
    const int oj = (j & 3) * U_ + (j >> 2);
    const int isdec = blockIdx.z;
    const float* R   = isdec ? decR : encR;
    const float* Kin = isdec ? decK : encK;
    const float* bi  = isdec ? decB : encB;
    __half* wf = isdec ? wfd : wfe;
    float*  bp = isdec ? bpd : bpe;
    const int Kx = isdec ? DIN : EIN;
    float v = 0.f;
    if (k < U_)                      v = R[(size_t)k * G_ + oj];
    else if (k >= HS && k < HS + Kx) v = Kin[(size_t)(k - HS) * G_ + oj];
    wf[(size_t)j * KAP + k] = __float2half_rn(v);
    if (k == 0) bp[j] = bi[oj];
}

__global__ void transpose_h_kernel(const float* __restrict__ in,
                                   __half* __restrict__ out,
                                   int R, int Cc, int ldo)
{
    __shared__ float t[32][33];
    const int c0 = blockIdx.x * 32, r0 = blockIdx.y * 32;
    const int x = threadIdx.x, y = threadIdx.y;
#pragma unroll
    for (int dy = 0; dy < 32; dy += 8) {
        const int r = r0 + y + dy, c = c0 + x;
        t[y + dy][x] = (r < R && c < Cc) ? in[(size_t)r * Cc + c] : 0.f;
    }
    __syncthreads();
#pragma unroll
    for (int dy = 0; dy < 32; dy += 8) {
        const int r = c0 + y + dy, c = r0 + x;
        if (r < Cc && c < ldo)
            out[(size_t)r * ldo + c] = __float2half_rn(c < R ? t[x][y + dy] : 0.f);
    }
}

__global__ void zero_hc_kernel(__half* h, float* c)
{
    const int i = blockIdx.x * 256 + threadIdx.x;
    if (i < B_ * HS) h[i] = __float2half_rn(0.f);
    if (i < B_ * U_) c[i] = 0.f;
}

// ==================== host orchestration ====================
extern "C" void kernel_launch(void* const* d_in, const int* in_sizes, int n_in,
                              void* d_out, int out_size)
{
    const float* x    = (const float*)d_in[0];
    const float* m    = (const float*)d_in[1];
    const float* encK = (const float*)d_in[2];
    const float* encR = (const float*)d_in[3];
    const float* encB = (const float*)d_in[4];
    const float* decK = (const float*)d_in[5];
    const float* decR = (const float*)d_in[6];
    const float* decB = (const float*)d_in[7];
    const float* Wmap = (const float*)d_in[8];
    const float* bmap = (const float*)d_in[9];
    const float* W1   = (const float*)d_in[10];
    const float* b1   = (const float*)d_in[11];
    const float* W2   = (const float*)d_in[12];
    const float* b2   = (const float*)d_in[13];
    const float* Wo   = (const float*)d_in[14];
    const float* bo   = (const float*)d_in[15];
    float* out = (float*)d_out;

    __half *h0, *h1, *dec, *t1, *t2, *xe, *xd, *wfe, *wfd, *wT;
    float *c, *bpe, *bpd;
    cudaGetSymbolAddress((void**)&h0,  g_h0);
    cudaGetSymbolAddress((void**)&h1,  g_h1);
    cudaGetSymbolAddress((void**)&c,   g_c);
    cudaGetSymbolAddress((void**)&dec, g_dec);
    cudaGetSymbolAddress((void**)&t1,  g_t1);
    cudaGetSymbolAddress((void**)&t2,  g_t2);
    cudaGetSymbolAddress((void**)&xe,  g_xe);
    cudaGetSymbolAddress((void**)&xd,  g_xd);
    cudaGetSymbolAddress((void**)&wfe, g_wfe);
    cudaGetSymbolAddress((void**)&wfd, g_wfd);
    cudaGetSymbolAddress((void**)&bpe, g_bpe);
    cudaGetSymbolAddress((void**)&bpd, g_bpd);
    cudaGetSymbolAddress((void**)&wT,  g_wT);

    cudaFuncSetAttribute(lstm_step<0>, cudaFuncAttributeMaxDynamicSharedMemorySize, DSMEM);
    cudaFuncSetAttribute(lstm_step<1>, cudaFuncAttributeMaxDynamicSharedMemorySize, DSMEM);
    cudaFuncSetAttribute(hgemm<1, __half>, cudaFuncAttributeMaxDynamicSharedMemorySize, DSMEM);
    cudaFuncSetAttribute(hgemm<2, __half>, cudaFuncAttributeMaxDynamicSharedMemorySize, DSMEM);
    cudaFuncSetAttribute(hgemm<0, float>,  cudaFuncAttributeMaxDynamicSharedMemorySize, DSMEM);

    // ---- prep: exactly 3 launches, so first lstm_step = stream launch #3 ----
    {
        const int n2 = 2 * B_ * T_ * XS;
        cvt_both_kernel<<<(n2 + 255) / 256, 256>>>(x, m, xe, xd);          // 0
    }
    build_wf_both_kernel<<<dim3((KAP + 255) / 256, G_, 2), 256>>>(
        encR, encK, encB, decR, decK, decB, wfe, wfd, bpe, bpd);           // 1
    {
        const int n = B_ * HS;
        zero_hc_kernel<<<(n + 255) / 256, 256>>>(h0, c);                   // 2
    }

    const dim3 grS((G_ + 127) / 128, B_ / 128);   // (12, 256)
    __half* hc = h0;
    __half* hn = h1;

    // encoder
    for (int t = 0; t < T_; t++) {
        lstm_step<0><<<grS, 256, DSMEM>>>(hc, xe + t * XS, wfe, bpe,
                                          hn, c, (__half*)nullptr, 0);
        __half* tmp = hc; hc = hn; hn = tmp;
    }
    // decoder
    for (int t = 0; t < T_; t++) {
        lstm_step<1><<<grS, 256, DSMEM>>>(hc, xd + t * XS, wfd, bpd,
                                          hn, c, dec, t * U_);
        __half* tmp = hc; hc = hn; hn = tmp;
    }

    // head weight transposes
    {
        dim3 tb(32, 8);
        transpose_h_kernel<<<dim3((H1_+31)/32, (DECS+31)/32), tb>>>(Wmap, wT+WT_MAP, T_*U_, H1_, DECS);
        transpose_h_kernel<<<dim3((H1_+31)/32, (H1_+31)/32),  tb>>>(W1, wT+WT_W1, H1_, H1_, H1_);
        transpose_h_kernel<<<dim3((H1_+31)/32, (H1_+31)/32),  tb>>>(W2, wT+WT_W2, H1_, H1_, H1_);
        transpose_h_kernel<<<dim3((OUT_+31)/32, (H1_+31)/32), tb>>>(Wo, wT+WT_WO, H1_, OUT_, H1_);
    }

    // dense head
    const dim3 grH((H1_ + 127) / 128, B_ / 128);
    const dim3 grO((OUT_ + 127) / 128, B_ / 128);
    hgemm<1, __half><<<grH, 256, DSMEM>>>(dec, DECS, wT + WT_MAP, DECS,
                                          t1, H1_, bmap, H1_, DECS);
    hgemm<2, __half><<<grH, 256, DSMEM>>>(t1, H1_, wT + WT_W1, H1_,
                                          t2, H1_, b1, H1_, H1_);
    hgemm<2, __half><<<grH, 256, DSMEM>>>(t2, H1_, wT + WT_W2, H1_,
                                          t1, H1_, b2, H1_, H1_);
    hgemm<0, float><<<grO, 256, DSMEM>>>(t1, H1_, wT + WT_WO, H1_,
                                         out, OUT_, bo, OUT_, H1_);
}

// round 13
// speedup vs baseline: 1.5660x; 1.0838x over previous
#include <cuda_runtime.h>
#include <cuda_fp16.h>
#include <math.h>
#include <stdint.h>

// ---------------- problem constants ----------------
#define B_   32768
#define T_   7
#define EIN  60
#define DIN  36
#define U_   356
#define G_   1424          // 4*U
#define H1_  768
#define OUT_ 168
#define HS   360           // padded h width (halves)
#define XS   64            // padded x width
#define KAP  448           // fused K padded
#define DECS 2496          // padded dec row
#define NCKS (KAP / 32)    // 14 (even)

// ---------------- scratch (device globals) ----------------------------
__device__ __align__(16) __half g_h0 [(size_t)B_ * HS];
__device__ __align__(16) __half g_h1 [(size_t)B_ * HS];
__device__ __align__(16) float  g_c  [(size_t)B_ * U_];
__device__ __align__(16) __half g_dec[(size_t)B_ * DECS];
__device__ __align__(16) __half g_t1 [(size_t)B_ * H1_];
__device__ __align__(16) __half g_t2 [(size_t)B_ * H1_];
__device__ __align__(16) __half g_xe [(size_t)B_ * T_ * XS];
__device__ __align__(16) __half g_xd [(size_t)B_ * T_ * XS];
__device__ __align__(16) __half g_wfe[(size_t)G_ * KAP];
__device__ __align__(16) __half g_wfd[(size_t)G_ * KAP];
__device__ __align__(16) float  g_bpe[G_];
__device__ __align__(16) float  g_bpd[G_];
#define WT_MAP  0
#define WT_W1   (WT_MAP + 768*DECS)
#define WT_W2   (WT_W1  + 768*768)
#define WT_WO   (WT_W2  + 768*768)
#define WT_TOTAL (WT_WO + 168*768)
__device__ __align__(16) __half g_wT[WT_TOTAL];

// ==================== helpers ====================
__device__ __forceinline__ uint32_t smem_u32(const void* p) {
    uint32_t a;
    asm("{ .reg .u64 t; cvta.to.shared.u64 t, %1; cvt.u32.u64 %0, t; }"
        : "=r"(a) : "l"(p));
    return a;
}
__device__ __forceinline__ void cpa16(uint32_t dst, const void* src, uint32_t sz) {
    asm volatile("cp.async.cg.shared.global [%0], [%1], 16, %2;"
                 :: "r"(dst), "l"(src), "r"(sz));
}
__device__ __forceinline__ void cpa_commit() {
    asm volatile("cp.async.commit_group;" ::: "memory");
}
__device__ __forceinline__ void cpa_wait_all() {
    asm volatile("cp.async.wait_group 0;" ::: "memory");
}
#define LDSM_X4(r0, r1, r2, r3, addr)                                          \
    asm volatile("ldmatrix.sync.aligned.m8n8.x4.shared.b16 {%0,%1,%2,%3}, [%4];" \
                 : "=r"(r0), "=r"(r1), "=r"(r2), "=r"(r3) : "r"(addr))
__device__ __forceinline__ void mma_f16(float c[4],
                                        uint32_t a0, uint32_t a1,
                                        uint32_t a2, uint32_t a3,
                                        uint32_t b0, uint32_t b1)
{
    asm volatile(
        "mma.sync.aligned.m16n8k16.row.col.f32.f16.f16.f32 "
        "{%0,%1,%2,%3}, {%4,%5,%6,%7}, {%8,%9}, {%0,%1,%2,%3};"
        : "+f"(c[0]), "+f"(c[1]), "+f"(c[2]), "+f"(c[3])
        : "r"(a0), "r"(a1), "r"(a2), "r"(a3), "r"(b0), "r"(b1));
}
__device__ __forceinline__ float htanh(float v) {
    float r;
    asm("tanh.approx.f32 %0, %1;" : "=f"(r) : "f"(v));
    return r;
}
__device__ __forceinline__ float hsig(float v) {
    return fmaf(htanh(v * 0.5f), 0.5f, 0.5f);
}
__device__ __forceinline__ void store2(__half* p, float x, float y) {
    *reinterpret_cast<__half2*>(p) = __floats2half2_rn(x, y);
}
__device__ __forceinline__ void store2(float* p, float x, float y) {
    *reinterpret_cast<float2*>(p) = make_float2(x, y);
}

// smem tile: 128 rows x 20 words (32 halves used + 8 pad), per operand
#define ROWW   20
#define TILE_W (128 * ROWW)          // words
#define STG_W  (2 * TILE_W)          // A+B per stage, words
#define NSTG   4
#define DSMEM  (NSTG * STG_W * 4)    // 81920 B  (x2 CTAs = 160KB < 228KB/SM)
#define ZSTR   132                   // epilogue z row stride (words)

// ==================== fused LSTM step (fp16, 128x128, 2 CTAs/SM) ==========
template<int WRITE_DEC>
__global__ void __launch_bounds__(256, 2)
lstm_step(const __half* __restrict__ hin,
          const __half* __restrict__ xin,       // + t*XS, stride T_*XS
          const __half* __restrict__ Wf,
          const float* __restrict__ bperm,
          __half* __restrict__ hout, float* __restrict__ cst,
          __half* __restrict__ dec, int dec_off)
{
    extern __shared__ __align__(16) char dynsmem[];
    const uint32_t sb = smem_u32(dynsmem);

    const int tid  = threadIdx.x;
    const int lane = tid & 31;
    const int w    = tid >> 5;
    const int m0   = blockIdx.y * 128;
    const int n0   = blockIdx.x * 128;

    const int wm = (w >> 2) * 64;
    const int wn = (w & 3) * 32;
    const int g  = lane >> 2;
    const int q4 = lane & 3;

    const int rs = tid >> 2;
    const int kq = tid & 3;

    const int a_off = (wm + (lane & 15)) * ROWW + (lane >> 4) * 4;
    const int b_off = (wn + (lane >> 4) * 8 + (lane & 7)) * ROWW
                    + ((lane >> 3) & 1) * 4;

    float acc[4][4][4];
#pragma unroll
    for (int i = 0; i < 4; i++)
#pragma unroll
        for (int j = 0; j < 4; j++)
#pragma unroll
            for (int q = 0; q < 4; q++) acc[i][j][q] = 0.f;

    auto issue = [&](int c) {
        const int s  = c & 3;
        const int kh = c * 32 + kq * 8;
        const uint32_t base = sb + (uint32_t)(s * STG_W * 4);
#pragma unroll
        for (int rr = 0; rr < 2; rr++) {
            const int r = rs + rr * 64;
            const uint32_t da = base + (uint32_t)(r * ROWW * 4 + kq * 16);
            const void* asrc;
            uint32_t asz = 16;
            if (kh < HS)            asrc = hin + (size_t)(m0 + r) * HS + kh;
            else if (kh < HS + XS)  asrc = xin + (size_t)(m0 + r) * (T_ * XS) + (kh - HS);
            else { asrc = hin; asz = 0; }
            cpa16(da, asrc, asz);
            const int n = n0 + r;
            const void* bsrc = (n < G_) ? (const void*)(Wf + (size_t)n * KAP + kh)
                                        : (const void*)Wf;
            cpa16(da + TILE_W * 4, bsrc, (n < G_) ? 16u : 0u);
        }
        cpa_commit();
    };

    issue(0); issue(1);

    for (int cc = 0; cc < NCKS; cc += 2) {
        cpa_wait_all();
        __syncthreads();
        if (cc + 2 < NCKS) { issue(cc + 2); issue(cc + 3); }

#pragma unroll
        for (int ci = 0; ci < 2; ci++) {
            const int c = cc + ci;
            const uint32_t abase = sb + (uint32_t)(((c & 3) * STG_W) * 4);
            const uint32_t bbase = abase + TILE_W * 4;
            uint32_t af[2][4][4], bf[2][4][2];
#pragma unroll
            for (int kg = 0; kg < 2; kg++) {
                const int kb = kg * 8;
#pragma unroll
                for (int mt = 0; mt < 4; mt++)
                    LDSM_X4(af[kg][mt][0], af[kg][mt][1],
                            af[kg][mt][2], af[kg][mt][3],
                            abase + (uint32_t)((a_off + mt * 16 * ROWW + kb) * 4));
#pragma unroll
                for (int p = 0; p < 2; p++)
                    LDSM_X4(bf[kg][2*p][0], bf[kg][2*p][1],
                            bf[kg][2*p+1][0], bf[kg][2*p+1][1],
                            bbase + (uint32_t)((b_off + p * 16 * ROWW + kb) * 4));
            }
#pragma unroll
            for (int kg = 0; kg < 2; kg++)
#pragma unroll
                for (int mt = 0; mt < 4; mt++)
#pragma unroll
                    for (int nt = 0; nt < 4; nt++)
                        mma_f16(acc[mt][nt],
                                af[kg][mt][0], af[kg][mt][1],
                                af[kg][mt][2], af[kg][mt][3],
                                bf[kg][nt][0], bf[kg][nt][1]);
        }
    }
    __syncthreads();   // mainloop smem dead; epilogue overlay begins

    // ---- epilogue: all warps dump z -> smem, one barrier, one cell pass ----
    float* zs = (float*)dynsmem;      // 128 x ZSTR floats = 67.6 KB
#pragma unroll
    for (int mt = 0; mt < 4; mt++) {
#pragma unroll
        for (int nt = 0; nt < 4; nt++) {
            const int col = n0 + wn + nt * 8 + 2 * q4;
            if (col >= G_) continue;
            const float bx = bperm[col], by = bperm[col + 1];
            const int cr = wn + nt * 8 + 2 * q4;
            const int rl = wm + mt * 16 + g;
            zs[rl * ZSTR + cr]           = acc[mt][nt][0] + bx;
            zs[rl * ZSTR + cr + 1]       = acc[mt][nt][1] + by;
            zs[(rl + 8) * ZSTR + cr]     = acc[mt][nt][2] + bx;
            zs[(rl + 8) * ZSTR + cr + 1] = acc[mt][nt][3] + by;
        }
    }
    __syncthreads();
    {
        const int ubase = n0 >> 2;
        const int ul = tid & 31;      // unit lane-fast (coalesced)
        const int rb = tid >> 5;      // 0..7
        const int unit = ubase + ul;
        if (unit < U_) {
#pragma unroll
            for (int rr = 0; rr < 16; rr++) {
                const int rl = rr * 8 + rb;
                const int b = m0 + rl;
                const float4 zv =
                    *reinterpret_cast<const float4*>(&zs[rl * ZSTR + ul * 4]);
                const float iv = hsig(zv.x);
                const float fv = hsig(zv.y);
                const float gv = htanh(zv.z);
                const float ov = hsig(zv.w);
                const size_t ci = (size_t)b * U_ + unit;
                const float cn = fv * cst[ci] + iv * gv;
                const float hn = ov * htanh(cn);
                cst[ci] = cn;
                hout[(size_t)b * HS + unit] = __float2half_rn(hn);
                if (WRITE_DEC)
                    dec[(size_t)b * DECS + dec_off + unit] = __float2half_rn(hn);
            }
        }
    }
}

// ==================== fp16 GEMM (head, 128x128, 2 CTAs/SM) ====================
// K must be a multiple of 64 (all call sites: 2496, 768, 768, 768).
template<int ACT, typename TO> // ACT: 0 none, 1 relu, 2 tanh
__global__ void __launch_bounds__(256, 2)
hgemm(const __half* __restrict__ A, int lda,
      const __half* __restrict__ Bt, int ldb,
      TO* __restrict__ C, int ldc,
      const float* __restrict__ bias,
      int N, int K)
{
    extern __shared__ __align__(16) char dynsmem[];
    const uint32_t sb = smem_u32(dynsmem);

    const int tid  = threadIdx.x;
    const int lane = tid & 31;
    const int w    = tid >> 5;
    const int m0   = blockIdx.y * 128;
    const int n0   = blockIdx.x * 128;

    const int wm = (w >> 2) * 64;
    const int wn = (w & 3) * 32;
    const int g  = lane >> 2;
    const int q4 = lane & 3;

    const int rs = tid >> 2;
    const int kq = tid & 3;

    const int a_off = (wm + (lane & 15)) * ROWW + (lane >> 4) * 4;
    const int b_off = (wn + (lane >> 4) * 8 + (lane & 7)) * ROWW
                    + ((lane >> 3) & 1) * 4;

    float acc[4][4][4];
#pragma unroll
    for (int i = 0; i < 4; i++)
#pragma unroll
        for (int j = 0; j < 4; j++)
#pragma unroll
            for (int q = 0; q < 4; q++) acc[i][j][q] = 0.f;

    const int nck = K >> 5;

    auto issue = [&](int c) {
        const int s  = c & 3;
        const int kh = c * 32 + kq * 8;
        const uint32_t base = sb + (uint32_t)(s * STG_W * 4);
#pragma unroll
        for (int rr = 0; rr < 2; rr++) {
            const int r = rs + rr * 64;
            const uint32_t da = base + (uint32_t)(r * ROWW * 4 + kq * 16);
            cpa16(da, A + (size_t)(m0 + r) * lda + kh, 16);
            const int n = n0 + r;
            const void* bsrc = (n < N) ? (const void*)(Bt + (size_t)n * ldb + kh)
                                       : (const void*)Bt;
            cpa16(da + TILE_W * 4, bsrc, (n < N) ? 16u : 0u);
        }
        cpa_commit();
    };

    issue(0); issue(1);

    for (int cc = 0; cc < nck; cc += 2) {
        cpa_wait_all();
        __syncthreads();
        if (cc + 2 < nck) { issue(cc + 2); issue(cc + 3); }

#pragma unroll
        for (int ci = 0; ci < 2; ci++) {
            const int c = cc + ci;
            const uint32_t abase = sb + (uint32_t)(((c & 3) * STG_W) * 4);
            const uint32_t bbase = abase + TILE_W * 4;
            uint32_t af[2][4][4], bf[2][4][2];
#pragma unroll
            for (int kg = 0; kg < 2; kg++) {
                const int kb = kg * 8;
#pragma unroll
                for (int mt = 0; mt < 4; mt++)
                    LDSM_X4(af[kg][mt][0], af[kg][mt][1],
                            af[kg][mt][2], af[kg][mt][3],
                            abase + (uint32_t)((a_off + mt * 16 * ROWW + kb) * 4));
#pragma unroll
                for (int p = 0; p < 2; p++)
                    LDSM_X4(bf[kg][2*p][0], bf[kg][2*p][1],
                            bf[kg][2*p+1][0], bf[kg][2*p+1][1],
                            bbase + (uint32_t)((b_off + p * 16 * ROWW + kb) * 4));
            }
#pragma unroll
            for (int kg = 0; kg < 2; kg++)
#pragma unroll
                for (int mt = 0; mt < 4; mt++)
#pragma unroll
                    for (int nt = 0; nt < 4; nt++)
                        mma_f16(acc[mt][nt],
                                af[kg][mt][0], af[kg][mt][1],
                                af[kg][mt][2], af[kg][mt][3],
                                bf[kg][nt][0], bf[kg][nt][1]);
        }
    }

#pragma unroll
    for (int mt = 0; mt < 4; mt++) {
#pragma unroll
        for (int nt = 0; nt < 4; nt++) {
            const int col = n0 + wn + nt * 8 + 2 * q4;
            if (col >= N) continue;
            const float bx = bias ? bias[col] : 0.f;
            const float by = bias ? bias[col + 1] : 0.f;
#pragma unroll
            for (int half = 0; half < 2; half++) {
                const int row = m0 + wm + mt * 16 + g + half * 8;
                float vx = acc[mt][nt][half * 2 + 0] + bx;
                float vy = acc[mt][nt][half * 2 + 1] + by;
                if (ACT == 1) { vx = fmaxf(vx, 0.f); vy = fmaxf(vy, 0.f); }
                if (ACT == 2) { vx = htanh(vx); vy = htanh(vy); }
                store2(&C[(size_t)row * ldc + col], vx, vy);
            }
        }
    }
}

// ==================== prep kernels (3 launches total) ====================
__global__ void cvt_both_kernel(const float* __restrict__ x,
                                const float* __restrict__ m,
                                __half* __restrict__ xe,
                                __half* __restrict__ xd)
{
    const int n = B_ * T_ * XS;
    const int i = blockIdx.x * 256 + threadIdx.x;
    if (i < n) {
        const int j = i & (XS - 1);
        const int bt = i >> 6;
        xe[i] = (j < EIN) ? __float2half_rn(x[(size_t)bt * EIN + j])
                          : __float2half_rn(0.f);
    } else if (i < 2 * n) {
        const int k = i - n;
        const int j = k & (XS - 1);
        const int bt = k >> 6;
        xd[k] = (j < DIN) ? __float2half_rn(m[(size_t)bt * DIN + j])
                          : __float2half_rn(0.f);
    }
}

__global__ void build_wf_both_kernel(const float* __restrict__ encR,
                                     const float* __restrict__ encK,
                                     const float* __restrict__ encB,
                                     const float* __restrict__ decR,
                                     const float* __restrict__ decK,
                                     const float* __restrict__ decB,
                                     __half* __restrict__ wfe,
                                     __half* __restrict__ wfd,
                                     float* __restrict__ bpe,
                                     float* __restrict__ bpd)
{
    const int j = blockIdx.y;
    const int k = blockIdx.x * 256 + threadIdx.x;
    if (k >= KAP) return;
    const int oj = (j & 3) * U_ + (j >> 2);
    const int isdec = blockIdx.z;
    const float* R   = isdec ? decR : encR;
    const float* Kin = isdec ? decK : encK;
    const float* bi  = isdec ? decB : encB;
    __half* wf = isdec ? wfd : wfe;
    float*  bp = isdec ? bpd : bpe;
    const int Kx = isdec ? DIN : EIN;
    float v = 0.f;
    if (k < U_)                      v = R[(size_t)k * G_ + oj];
    else if (k >= HS && k < HS + Kx) v = Kin[(size_t)(k - HS) * G_ + oj];
    wf[(size_t)j * KAP + k] = __float2half_rn(v);
    if (k == 0) bp[j] = bi[oj];
}

__global__ void transpose_h_kernel(const float* __restrict__ in,
                                   __half* __restrict__ out,
                                   int R, int Cc, int ldo)
{
    __shared__ float t[32][33];
    const int c0 = blockIdx.x * 32, r0 = blockIdx.y * 32;
    const int x = threadIdx.x, y = threadIdx.y;
#pragma unroll
    for (int dy = 0; dy < 32; dy += 8) {
        const int r = r0 + y + dy, c = c0 + x;
        t[y + dy][x] = (r < R && c < Cc) ? in[(size_t)r * Cc + c] : 0.f;
    }
    __syncthreads();
#pragma unroll
    for (int dy = 0; dy < 32; dy += 8) {
        const int r = c0 + y + dy, c = r0 + x;
        if (r < Cc && c < ldo)
            out[(size_t)r * ldo + c] = __float2half_rn(c < R ? t[x][y + dy] : 0.f);
    }
}

__global__ void zero_hc_kernel(__half* h, float* c)
{
    const int i = blockIdx.x * 256 + threadIdx.x;
    if (i < B_ * HS) h[i] = __float2half_rn(0.f);
    if (i < B_ * U_) c[i] = 0.f;
}

// ==================== host orchestration ====================
extern "C" void kernel_launch(void* const* d_in, const int* in_sizes, int n_in,
                              void* d_out, int out_size)
{
    const float* x    = (const float*)d_in[0];
    const float* m    = (const float*)d_in[1];
    const float* encK = (const float*)d_in[2];
    const float* encR = (const float*)d_in[3];
    const float* encB = (const float*)d_in[4];
    const float* decK = (const float*)d_in[5];
    const float* decR = (const float*)d_in[6];
    const float* decB = (const float*)d_in[7];
    const float* Wmap = (const float*)d_in[8];
    const float* bmap = (const float*)d_in[9];
    const float* W1   = (const float*)d_in[10];
    const float* b1   = (const float*)d_in[11];
    const float* W2   = (const float*)d_in[12];
    const float* b2   = (const float*)d_in[13];
    const float* Wo   = (const float*)d_in[14];
    const float* bo   = (const float*)d_in[15];
    float* out = (float*)d_out;

    __half *h0, *h1, *dec, *t1, *t2, *xe, *xd, *wfe, *wfd, *wT;
    float *c, *bpe, *bpd;
    cudaGetSymbolAddress((void**)&h0,  g_h0);
    cudaGetSymbolAddress((void**)&h1,  g_h1);
    cudaGetSymbolAddress((void**)&c,   g_c);
    cudaGetSymbolAddress((void**)&dec, g_dec);
    cudaGetSymbolAddress((void**)&t1,  g_t1);
    cudaGetSymbolAddress((void**)&t2,  g_t2);
    cudaGetSymbolAddress((void**)&xe,  g_xe);
    cudaGetSymbolAddress((void**)&xd,  g_xd);
    cudaGetSymbolAddress((void**)&wfe, g_wfe);
    cudaGetSymbolAddress((void**)&wfd, g_wfd);
    cudaGetSymbolAddress((void**)&bpe, g_bpe);
    cudaGetSymbolAddress((void**)&bpd, g_bpd);
    cudaGetSymbolAddress((void**)&wT,  g_wT);

    cudaFuncSetAttribute(lstm_step<0>, cudaFuncAttributeMaxDynamicSharedMemorySize, DSMEM);
    cudaFuncSetAttribute(lstm_step<1>, cudaFuncAttributeMaxDynamicSharedMemorySize, DSMEM);
    cudaFuncSetAttribute(hgemm<1, __half>, cudaFuncAttributeMaxDynamicSharedMemorySize, DSMEM);
    cudaFuncSetAttribute(hgemm<2, __half>, cudaFuncAttributeMaxDynamicSharedMemorySize, DSMEM);
    cudaFuncSetAttribute(hgemm<0, float>,  cudaFuncAttributeMaxDynamicSharedMemorySize, DSMEM);

    // ---- prep: exactly 3 launches, so first lstm_step = stream launch #3 ----
    {
        const int n2 = 2 * B_ * T_ * XS;
        cvt_both_kernel<<<(n2 + 255) / 256, 256>>>(x, m, xe, xd);          // 0
    }
    build_wf_both_kernel<<<dim3((KAP + 255) / 256, G_, 2), 256>>>(
        encR, encK, encB, decR, decK, decB, wfe, wfd, bpe, bpd);           // 1
    {
        const int n = B_ * HS;
        zero_hc_kernel<<<(n + 255) / 256, 256>>>(h0, c);                   // 2
    }

    const dim3 grS((G_ + 127) / 128, B_ / 128);   // (12, 256)
    __half* hc = h0;
    __half* hn = h1;

    // encoder
    for (int t = 0; t < T_; t++) {
        lstm_step<0><<<grS, 256, DSMEM>>>(hc, xe + t * XS, wfe, bpe,
                                          hn, c, (__half*)nullptr, 0);
        __half* tmp = hc; hc = hn; hn = tmp;
    }
    // decoder
    for (int t = 0; t < T_; t++) {
        lstm_step<1><<<grS, 256, DSMEM>>>(hc, xd + t * XS, wfd, bpd,
                                          hn, c, dec, t * U_);
        __half* tmp = hc; hc = hn; hn = tmp;
    }

    // head weight transposes
    {
        dim3 tb(32, 8);
        transpose_h_kernel<<<dim3((H1_+31)/32, (DECS+31)/32), tb>>>(Wmap, wT+WT_MAP, T_*U_, H1_, DECS);
        transpose_h_kernel<<<dim3((H1_+31)/32, (H1_+31)/32),  tb>>>(W1, wT+WT_W1, H1_, H1_, H1_);
        transpose_h_kernel<<<dim3((H1_+31)/32, (H1_+31)/32),  tb>>>(W2, wT+WT_W2, H1_, H1_, H1_);
        transpose_h_kernel<<<dim3((OUT_+31)/32, (H1_+31)/32), tb>>>(Wo, wT+WT_WO, H1_, OUT_, H1_);
    }

    // dense head
    const dim3 grH((H1_ + 127) / 128, B_ / 128);
    const dim3 grO((OUT_ + 127) / 128, B_ / 128);
    hgemm<1, __half><<<grH, 256, DSMEM>>>(dec, DECS, wT + WT_MAP, DECS,
                                          t1, H1_, bmap, H1_, DECS);
    hgemm<2, __half><<<grH, 256, DSMEM>>>(t1, H1_, wT + WT_W1, H1_,
                                          t2, H1_, b1, H1_, H1_);
    hgemm<2, __half><<<grH, 256, DSMEM>>>(t2, H1_, wT + WT_W2, H1_,
                                          t1, H1_, b2, H1_, H1_);
    hgemm<0, float><<<grO, 256, DSMEM>>>(t1, H1_, wT + WT_WO, H1_,
                                         out, OUT_, bo, OUT_, H1_);
}

// round 14
// speedup vs baseline: 1.6156x; 1.0316x over previous
#include <cuda_runtime.h>
#include <cuda_fp16.h>
#include <math.h>
#include <stdint.h>

// ---------------- problem constants ----------------
#define B_   32768
#define T_   7
#define EIN  60
#define DIN  36
#define U_   356
#define G_   1424          // 4*U
#define H1_  768
#define OUT_ 168
#define HS   360           // padded h width (halves, mult of 8)
#define XS   64            // padded x width
#define KAP  448           // fused K padded
#define DECS 2496          // padded dec row
#define NCKS (KAP / 32)    // 14

// ---------------- scratch (device globals) ----------------------------
__device__ __align__(16) __half g_h0 [(size_t)B_ * HS];
__device__ __align__(16) __half g_h1 [(size_t)B_ * HS];
__device__ __align__(16) float  g_c  [(size_t)B_ * U_];
__device__ __align__(16) __half g_dec[(size_t)B_ * DECS];
__device__ __align__(16) __half g_t1 [(size_t)B_ * H1_];
__device__ __align__(16) __half g_t2 [(size_t)B_ * H1_];
__device__ __align__(16) __half g_xe [(size_t)B_ * T_ * XS];
__device__ __align__(16) __half g_xd [(size_t)B_ * T_ * XS];
__device__ __align__(16) __half g_wfe[(size_t)G_ * KAP];
__device__ __align__(16) __half g_wfd[(size_t)G_ * KAP];
__device__ __align__(16) float  g_bpe[G_];
__device__ __align__(16) float  g_bpd[G_];
#define WT_MAP  0
#define WT_W1   (WT_MAP + 768*DECS)
#define WT_W2   (WT_W1  + 768*768)
#define WT_WO   (WT_W2  + 768*768)
#define WT_TOTAL (WT_WO + 168*768)
__device__ __align__(16) __half g_wT[WT_TOTAL];

// ==================== helpers ====================
__device__ __forceinline__ uint32_t smem_u32(const void* p) {
    uint32_t a;
    asm("{ .reg .u64 t; cvta.to.shared.u64 t, %1; cvt.u32.u64 %0, t; }"
        : "=r"(a) : "l"(p));
    return a;
}
__device__ __forceinline__ void cpa16(uint32_t dst, const void* src, uint32_t sz) {
    asm volatile("cp.async.cg.shared.global [%0], [%1], 16, %2;"
                 :: "r"(dst), "l"(src), "r"(sz));
}
__device__ __forceinline__ void cpa_commit() {
    asm volatile("cp.async.commit_group;" ::: "memory");
}
__device__ __forceinline__ void cpa_wait_all() {
    asm volatile("cp.async.wait_group 0;" ::: "memory");
}
#define MBAR_INIT(a, c) \
    asm volatile("mbarrier.init.shared.b64 [%0], %1;" :: "r"(a), "r"(c) : "memory")
#define MBAR_ARRIVE(a) \
    asm volatile("mbarrier.arrive.shared.b64 _, [%0];" :: "r"(a) : "memory")
#define MBAR_ARRIVE_CPA(a) \
    asm volatile("cp.async.mbarrier.arrive.noinc.shared.b64 [%0];" :: "r"(a) : "memory")
#define MBAR_WAIT(mbar, ph) do {                                               \
    uint32_t _m = (mbar); uint32_t _p = (ph); uint32_t _d;                     \
    asm volatile("{\n\t.reg .pred p;\n\t"                                      \
        "mbarrier.try_wait.parity.acquire.cta.shared::cta.b64 p, [%1], %2;\n\t"\
        "selp.b32 %0, 1, 0, p;\n\t}"                                           \
        : "=r"(_d) : "r"(_m), "r"(_p) : "memory");                             \
    if (!_d) {                                                                 \
        asm volatile("{\n\t.reg .pred P1;\n\t"                                 \
            "WL_%=:\n\t"                                                       \
            "mbarrier.try_wait.parity.acquire.cta.shared::cta.b64 P1, [%0], %1, 0x989680;\n\t" \
            "@P1 bra.uni WD_%=;\n\t"                                           \
            "bra.uni WL_%=;\n\t"                                               \
            "WD_%=:\n\t}"                                                      \
            :: "r"(_m), "r"(_p) : "memory");                                   \
    }                                                                          \
} while (0)
#define LDSM_X4(r0, r1, r2, r3, addr)                                          \
    asm volatile("ldmatrix.sync.aligned.m8n8.x4.shared.b16 {%0,%1,%2,%3}, [%4];" \
                 : "=r"(r0), "=r"(r1), "=r"(r2), "=r"(r3) : "r"(addr))
__device__ __forceinline__ void mma_f16(float c[4],
                                        uint32_t a0, uint32_t a1,
                                        uint32_t a2, uint32_t a3,
                                        uint32_t b0, uint32_t b1)
{
    asm volatile(
        "mma.sync.aligned.m16n8k16.row.col.f32.f16.f16.f32 "
        "{%0,%1,%2,%3}, {%4,%5,%6,%7}, {%8,%9}, {%0,%1,%2,%3};"
        : "+f"(c[0]), "+f"(c[1]), "+f"(c[2]), "+f"(c[3])
        : "r"(a0), "r"(a1), "r"(a2), "r"(a3), "r"(b0), "r"(b1));
}
__device__ __forceinline__ float htanh(float v) {
    float r;
    asm("tanh.approx.f32 %0, %1;" : "=f"(r) : "f"(v));
    return r;
}
__device__ __forceinline__ float hsig(float v) {
    return fmaf(htanh(v * 0.5f), 0.5f, 0.5f);
}
__device__ __forceinline__ void store2(__half* p, float x, float y) {
    *reinterpret_cast<__half2*>(p) = __floats2half2_rn(x, y);
}
__device__ __forceinline__ void store2(float* p, float x, float y) {
    *reinterpret_cast<float2*>(p) = make_float2(x, y);
}

// smem tile: 128 rows x 20 words (32 halves + 8 pad words), per operand
#define ROWW    20
#define ROWB    80                    // bytes per row
#define TILE_B  (128 * ROWB)          // 10240 bytes
#define STG_B   (2 * TILE_B)          // 20480 bytes (A+B)
#define NSTG_S  5                     // lstm_step stages
#define DSMEM_S (NSTG_S * STG_B)      // 102400 B (x2 CTAs = 204.8KB)
#define NSTG_H  4                     // hgemm stages
#define DSMEM_H (NSTG_H * STG_B)      // 81920 B
#define ZSTR    132                   // epilogue z row stride (words)

// ==================== fused LSTM step: warp-specialized pipeline ==========
// 288 threads: warps 0-7 = consumers (128x128 tile, 64x32 warp tiles),
// warp 8 = cp.async producer. Per-stage mbarrier full/empty; no block
// barriers in the mainloop.
template<int WRITE_DEC>
__global__ void __launch_bounds__(288, 2)
lstm_step(const __half* __restrict__ hin,
          const __half* __restrict__ xin,       // + t*XS, stride T_*XS
          const __half* __restrict__ Wf,
          const float* __restrict__ bperm,
          __half* __restrict__ hout, float* __restrict__ cst,
          __half* __restrict__ dec, int dec_off)
{
    extern __shared__ __align__(16) char dynsmem[];
    __shared__ __align__(8) unsigned long long s_mbar[2 * NSTG_S];
    const uint32_t sb = smem_u32(dynsmem);
    const uint32_t mb_full  = smem_u32(s_mbar);            // [s]
    const uint32_t mb_empty = mb_full + 8u * NSTG_S;       // [s]

    const int tid  = threadIdx.x;
    const int lane = tid & 31;
    const int w    = tid >> 5;                 // 0..8
    const int m0   = blockIdx.y * 128;
    const int n0   = blockIdx.x * 128;

    if (tid == 0) {
        for (int s = 0; s < NSTG_S; s++) {
            MBAR_INIT(mb_full  + 8u * s, 32);  // producer warp: 32 cpa-arrives
            MBAR_INIT(mb_empty + 8u * s, 8);   // 8 consumer warps
        }
    }
    __syncthreads();

    float acc[4][4][4];
    const int wm = (w >> 2) * 64;              // consumer-only meaning
    const int wn = (w & 3) * 32;
    const int g  = lane >> 2;
    const int q4 = lane & 3;

    if (w == 8) {
        // ---------------- producer warp ----------------
        const int seg = lane & 3;              // 16B segment within 32-half row
        const int r0p = lane >> 2;             // 0..7
        for (int c = 0; c < NCKS; c++) {
            const int s = c % NSTG_S;
            if (c >= NSTG_S)
                MBAR_WAIT(mb_empty + 8u * s, ((c / NSTG_S) - 1) & 1);
            const uint32_t base = sb + (uint32_t)(s * STG_B);
            const int kh = c * 32 + seg * 8;   // global k (halves), 8-aligned
            // A source select: uniform per (c, seg); never straddles regions
            const __half* abase_;
            size_t astr;
            uint32_t aval;
            if (kh < HS)           { abase_ = hin + kh;        astr = HS;          aval = 16u; }
            else if (kh < HS + XS) { abase_ = xin + (kh - HS); astr = T_ * XS;     aval = 16u; }
            else                   { abase_ = hin;             astr = 0;           aval = 0u;  }
            const __half* bbase_ = Wf + kh;
#pragma unroll
            for (int i = 0; i < 16; i++) {
                const int row = r0p + i * 8;   // 0..127
                const uint32_t da = base + (uint32_t)(row * ROWB + seg * 16);
                cpa16(da, abase_ + (size_t)(m0 + row) * astr, aval);
                const int n = n0 + row;
                const uint32_t bv = (n < G_) ? 16u : 0u;
                cpa16(da + TILE_B, bv ? (const void*)(bbase_ + (size_t)n * KAP)
                                      : (const void*)Wf, bv);
            }
            MBAR_ARRIVE_CPA(mb_full + 8u * s);
        }
    } else {
        // ---------------- consumer warps (0..7) ----------------
        const int a_off = (wm + (lane & 15)) * ROWW + (lane >> 4) * 4;
        const int b_off = (wn + (lane >> 4) * 8 + (lane & 7)) * ROWW
                        + ((lane >> 3) & 1) * 4;
#pragma unroll
        for (int i = 0; i < 4; i++)
#pragma unroll
            for (int j = 0; j < 4; j++)
#pragma unroll
                for (int q = 0; q < 4; q++) acc[i][j][q] = 0.f;

        for (int c = 0; c < NCKS; c++) {
            const int s = c % NSTG_S;
            MBAR_WAIT(mb_full + 8u * s, (c / NSTG_S) & 1);
            const uint32_t abase = sb + (uint32_t)(s * STG_B);
            const uint32_t bbase = abase + TILE_B;
#pragma unroll
            for (int kg = 0; kg < 2; kg++) {
                const int kb = kg * 8;
                uint32_t af[4][4], bf[4][2];
#pragma unroll
                for (int mt = 0; mt < 4; mt++)
                    LDSM_X4(af[mt][0], af[mt][1], af[mt][2], af[mt][3],
                            abase + (uint32_t)((a_off + mt * 16 * ROWW + kb) * 4));
#pragma unroll
                for (int p = 0; p < 2; p++)
                    LDSM_X4(bf[2*p][0], bf[2*p][1], bf[2*p+1][0], bf[2*p+1][1],
                            bbase + (uint32_t)((b_off + p * 16 * ROWW + kb) * 4));
                if (kg == 1 && lane == 0)      // all reads of stage s done
                    MBAR_ARRIVE(mb_empty + 8u * s);
#pragma unroll
                for (int mt = 0; mt < 4; mt++)
#pragma unroll
                    for (int nt = 0; nt < 4; nt++)
                        mma_f16(acc[mt][nt],
                                af[mt][0], af[mt][1], af[mt][2], af[mt][3],
                                bf[nt][0], bf[nt][1]);
            }
        }
    }
    __syncthreads();   // mainloop smem dead; epilogue overlay begins

    // ---- epilogue: consumer warps dump z -> smem, one barrier, cell pass ----
    float* zs = (float*)dynsmem;      // 128 x ZSTR floats = 67.6 KB
    if (w < 8) {
#pragma unroll
        for (int mt = 0; mt < 4; mt++) {
#pragma unroll
            for (int nt = 0; nt < 4; nt++) {
                const int col = n0 + wn + nt * 8 + 2 * q4;
                if (col >= G_) continue;
                const float bx = bperm[col], by = bperm[col + 1];
                const int cr = wn + nt * 8 + 2 * q4;
                const int rl = wm + mt * 16 + g;
                zs[rl * ZSTR + cr]           = acc[mt][nt][0] + bx;
                zs[rl * ZSTR + cr + 1]       = acc[mt][nt][1] + by;
                zs[(rl + 8) * ZSTR + cr]     = acc[mt][nt][2] + bx;
                zs[(rl + 8) * ZSTR + cr + 1] = acc[mt][nt][3] + by;
            }
        }
    }
    __syncthreads();
    if (tid < 256) {
        const int ubase = n0 >> 2;
        const int ul = tid & 31;      // unit lane-fast (coalesced)
        const int rb = tid >> 5;      // 0..7
        const int unit = ubase + ul;
        if (unit < U_) {
#pragma unroll
            for (int rr = 0; rr < 16; rr++) {
                const int rl = rr * 8 + rb;
                const int b = m0 + rl;
                const float4 zv =
                    *reinterpret_cast<const float4*>(&zs[rl * ZSTR + ul * 4]);
                const float iv = hsig(zv.x);
                const float fv = hsig(zv.y);
                const float gv = htanh(zv.z);
                const float ov = hsig(zv.w);
                const size_t ci = (size_t)b * U_ + unit;
                const float cn = fv * cst[ci] + iv * gv;
                const float hn = ov * htanh(cn);
                cst[ci] = cn;
                hout[(size_t)b * HS + unit] = __float2half_rn(hn);
                if (WRITE_DEC)
                    dec[(size_t)b * DECS + dec_off + unit] = __float2half_rn(hn);
            }
        }
    }
}

// ==================== fp16 GEMM (head, 128x128, 2 CTAs/SM) ====================
// K must be a multiple of 64 (call sites: 2496, 768, 768, 768).
template<int ACT, typename TO> // ACT: 0 none, 1 relu, 2 tanh
__global__ void __launch_bounds__(256, 2)
hgemm(const __half* __restrict__ A, int lda,
      const __half* __restrict__ Bt, int ldb,
      TO* __restrict__ C, int ldc,
      const float* __restrict__ bias,
      int N, int K)
{
    extern __shared__ __align__(16) char dynsmem[];
    const uint32_t sb = smem_u32(dynsmem);

    const int tid  = threadIdx.x;
    const int lane = tid & 31;
    const int w    = tid >> 5;
    const int m0   = blockIdx.y * 128;
    const int n0   = blockIdx.x * 128;

    const int wm = (w >> 2) * 64;
    const int wn = (w & 3) * 32;
    const int g  = lane >> 2;
    const int q4 = lane & 3;

    const int rs = tid >> 2;
    const int kq = tid & 3;

    const int a_off = (wm + (lane & 15)) * ROWW + (lane >> 4) * 4;
    const int b_off = (wn + (lane >> 4) * 8 + (lane & 7)) * ROWW
                    + ((lane >> 3) & 1) * 4;

    float acc[4][4][4];
#pragma unroll
    for (int i = 0; i < 4; i++)
#pragma unroll
        for (int j = 0; j < 4; j++)
#pragma unroll
            for (int q = 0; q < 4; q++) acc[i][j][q] = 0.f;

    const int nck = K >> 5;

    auto issue = [&](int c) {
        const int s  = c & 3;
        const int kh = c * 32 + kq * 8;
        const uint32_t base = sb + (uint32_t)(s * STG_B);
#pragma unroll
        for (int rr = 0; rr < 2; rr++) {
            const int r = rs + rr * 64;
            const uint32_t da = base + (uint32_t)(r * ROWB + kq * 16);
            cpa16(da, A + (size_t)(m0 + r) * lda + kh, 16);
            const int n = n0 + r;
            const void* bsrc = (n < N) ? (const void*)(Bt + (size_t)n * ldb + kh)
                                       : (const void*)Bt;
            cpa16(da + TILE_B, bsrc, (n < N) ? 16u : 0u);
        }
        cpa_commit();
    };

    issue(0); issue(1);

    for (int cc = 0; cc < nck; cc += 2) {
        cpa_wait_all();
        __syncthreads();
        if (cc + 2 < nck) { issue(cc + 2); issue(cc + 3); }

#pragma unroll
        for (int ci = 0; ci < 2; ci++) {
            const int c = cc + ci;
            const uint32_t abase = sb + (uint32_t)(((c & 3) * STG_B));
            const uint32_t bbase = abase + TILE_B;
            uint32_t af[2][4][4], bf[2][4][2];
#pragma unroll
            for (int kg = 0; kg < 2; kg++) {
                const int kb = kg * 8;
#pragma unroll
                for (int mt = 0; mt < 4; mt++)
                    LDSM_X4(af[kg][mt][0], af[kg][mt][1],
                            af[kg][mt][2], af[kg][mt][3],
                            abase + (uint32_t)((a_off + mt * 16 * ROWW + kb) * 4));
#pragma unroll
                for (int p = 0; p < 2; p++)
                    LDSM_X4(bf[kg][2*p][0], bf[kg][2*p][1],
                            bf[kg][2*p+1][0], bf[kg][2*p+1][1],
                            bbase + (uint32_t)((b_off + p * 16 * ROWW + kb) * 4));
            }
#pragma unroll
            for (int kg = 0; kg < 2; kg++)
#pragma unroll
                for (int mt = 0; mt < 4; mt++)
#pragma unroll
                    for (int nt = 0; nt < 4; nt++)
                        mma_f16(acc[mt][nt],
                                af[kg][mt][0], af[kg][mt][1],
                                af[kg][mt][2], af[kg][mt][3],
                                bf[kg][nt][0], bf[kg][nt][1]);
        }
    }

#pragma unroll
    for (int mt = 0; mt < 4; mt++) {
#pragma unroll
        for (int nt = 0; nt < 4; nt++) {
            const int col = n0 + wn + nt * 8 + 2 * q4;
            if (col >= N) continue;
            const float bx = bias ? bias[col] : 0.f;
            const float by = bias ? bias[col + 1] : 0.f;
#pragma unroll
            for (int half = 0; half < 2; half++) {
                const int row = m0 + wm + mt * 16 + g + half * 8;
                float vx = acc[mt][nt][half * 2 + 0] + bx;
                float vy = acc[mt][nt][half * 2 + 1] + by;
                if (ACT == 1) { vx = fmaxf(vx, 0.f); vy = fmaxf(vy, 0.f); }
                if (ACT == 2) { vx = htanh(vx); vy = htanh(vy); }
                store2(&C[(size_t)row * ldc + col], vx, vy);
            }
        }
    }
}

// ==================== prep kernels (3 launches total) ====================
__global__ void cvt_both_kernel(const float* __restrict__ x,
                                const float* __restrict__ m,
                                __half* __restrict__ xe,
                                __half* __restrict__ xd)
{
    const int n = B_ * T_ * XS;
    const int i = blockIdx.x * 256 + threadIdx.x;
    if (i < n) {
        const int j = i & (XS - 1);
        const int bt = i >> 6;
        xe[i] = (j < EIN) ? __float2half_rn(x[(size_t)bt * EIN + j])
                          : __float2half_rn(0.f);
    } else if (i < 2 * n) {
        const int k = i - n;
        const int j = k & (XS - 1);
        const int bt = k >> 6;
        xd[k] = (j < DIN) ? __float2half_rn(m[(size_t)bt * DIN + j])
                          : __float2half_rn(0.f);
    }
}

__global__ void build_wf_both_kernel(const float* __restrict__ encR,
                                     const float* __restrict__ encK,
                                     const float* __restrict__ encB,
                                     const float* __restrict__ decR,
                                     const float* __restrict__ decK,
                                     const float* __restrict__ decB,
                                     __half* __restrict__ wfe,
                                     __half* __restrict__ wfd,
                                     float* __restrict__ bpe,
                                     float* __restrict__ bpd)
{
    const int j = blockIdx.y;
    const int k = blockIdx.x * 256 + threadIdx.x;
    if (k >= KAP) return;
    const int oj = (j & 3) * U_ + (j >> 2);
    const int isdec = blockIdx.z;
    const float* R   = isdec ? decR : encR;
    const float* Kin = isdec ? decK : encK;
    const float* bi  = isdec ? decB : encB;
    __half* wf = isdec ? wfd : wfe;
    float*  bp = isdec ? bpd : bpe;
    const int Kx = isdec ? DIN : EIN;
    float v = 0.f;
    if (k < U_)                      v = R[(size_t)k * G_ + oj];
    else if (k >= HS && k < HS + Kx) v = Kin[(size_t)(k - HS) * G_ + oj];
    wf[(size_t)j * KAP + k] = __float2half_rn(v);
    if (k == 0) bp[j] = bi[oj];
}

__global__ void transpose_h_kernel(const float* __restrict__ in,
                                   __half* __restrict__ out,
                                   int R, int Cc, int ldo)
{
    __shared__ float t[32][33];
    const int c0 = blockIdx.x * 32, r0 = blockIdx.y * 32;
    const int x = threadIdx.x, y = threadIdx.y;
#pragma unroll
    for (int dy = 0; dy < 32; dy += 8) {
        const int r = r0 + y + dy, c = c0 + x;
        t[y + dy][x] = (r < R && c < Cc) ? in[(size_t)r * Cc + c] : 0.f;
    }
    __syncthreads();
#pragma unroll
    for (int dy = 0; dy < 32; dy += 8) {
        const int r = c0 + y + dy, c = r0 + x;
        if (r < Cc && c < ldo)
            out[(size_t)r * ldo + c] = __float2half_rn(c < R ? t[x][y + dy] : 0.f);
    }
}

__global__ void zero_hc_kernel(__half* h, float* c)
{
    const int i = blockIdx.x * 256 + threadIdx.x;
    if (i < B_ * HS) h[i] = __float2half_rn(0.f);
    if (i < B_ * U_) c[i] = 0.f;
}

// ==================== host orchestration ====================
extern "C" void kernel_launch(void* const* d_in, const int* in_sizes, int n_in,
                              void* d_out, int out_size)
{
    const float* x    = (const float*)d_in[0];
    const float* m    = (const float*)d_in[1];
    const float* encK = (const float*)d_in[2];
    const float* encR = (const float*)d_in[3];
    const float* encB = (const float*)d_in[4];
    const float* decK = (const float*)d_in[5];
    const float* decR = (const float*)d_in[6];
    const float* decB = (const float*)d_in[7];
    const float* Wmap = (const float*)d_in[8];
    const float* bmap = (const float*)d_in[9];
    const float* W1   = (const float*)d_in[10];
    const float* b1   = (const float*)d_in[11];
    const float* W2   = (const float*)d_in[12];
    const float* b2   = (const float*)d_in[13];
    const float* Wo   = (const float*)d_in[14];
    const float* bo   = (const float*)d_in[15];
    float* out = (float*)d_out;

    __half *h0, *h1, *dec, *t1, *t2, *xe, *xd, *wfe, *wfd, *wT;
    float *c, *bpe, *bpd;
    cudaGetSymbolAddress((void**)&h0,  g_h0);
    cudaGetSymbolAddress((void**)&h1,  g_h1);
    cudaGetSymbolAddress((void**)&c,   g_c);
    cudaGetSymbolAddress((void**)&dec, g_dec);
    cudaGetSymbolAddress((void**)&t1,  g_t1);
    cudaGetSymbolAddress((void**)&t2,  g_t2);
    cudaGetSymbolAddress((void**)&xe,  g_xe);
    cudaGetSymbolAddress((void**)&xd,  g_xd);
    cudaGetSymbolAddress((void**)&wfe, g_wfe);
    cudaGetSymbolAddress((void**)&wfd, g_wfd);
    cudaGetSymbolAddress((void**)&bpe, g_bpe);
    cudaGetSymbolAddress((void**)&bpd, g_bpd);
    cudaGetSymbolAddress((void**)&wT,  g_wT);

    cudaFuncSetAttribute(lstm_step<0>, cudaFuncAttributeMaxDynamicSharedMemorySize, DSMEM_S);
    cudaFuncSetAttribute(lstm_step<1>, cudaFuncAttributeMaxDynamicSharedMemorySize, DSMEM_S);
    cudaFuncSetAttribute(hgemm<1, __half>, cudaFuncAttributeMaxDynamicSharedMemorySize, DSMEM_H);
    cudaFuncSetAttribute(hgemm<2, __half>, cudaFuncAttributeMaxDynamicSharedMemorySize, DSMEM_H);
    cudaFuncSetAttribute(hgemm<0, float>,  cudaFuncAttributeMaxDynamicSharedMemorySize, DSMEM_H);

    // ---- prep: exactly 3 launches, so first lstm_step = stream launch #3 ----
    {
        const int n2 = 2 * B_ * T_ * XS;
        cvt_both_kernel<<<(n2 + 255) / 256, 256>>>(x, m, xe, xd);          // 0
    }
    build_wf_both_kernel<<<dim3((KAP + 255) / 256, G_, 2), 256>>>(
        encR, encK, encB, decR, decK, decB, wfe, wfd, bpe, bpd);           // 1
    {
        const int n = B_ * HS;
        zero_hc_kernel<<<(n + 255) / 256, 256>>>(h0, c);                   // 2
    }

    const dim3 grS((G_ + 127) / 128, B_ / 128);   // (12, 256)
    __half* hc = h0;
    __half* hn = h1;

    // encoder
    for (int t = 0; t < T_; t++) {
        lstm_step<0><<<grS, 288, DSMEM_S>>>(hc, xe + t * XS, wfe, bpe,
                                            hn, c, (__half*)nullptr, 0);
        __half* tmp = hc; hc = hn; hn = tmp;
    }
    // decoder
    for (int t = 0; t < T_; t++) {
        lstm_step<1><<<grS, 288, DSMEM_S>>>(hc, xd + t * XS, wfd, bpd,
                                            hn, c, dec, t * U_);
        __half* tmp = hc; hc = hn; hn = tmp;
    }

    // head weight transposes
    {
        dim3 tb(32, 8);
        transpose_h_kernel<<<dim3((H1_+31)/32, (DECS+31)/32), tb>>>(Wmap, wT+WT_MAP, T_*U_, H1_, DECS);
        transpose_h_kernel<<<dim3((H1_+31)/32, (H1_+31)/32),  tb>>>(W1, wT+WT_W1, H1_, H1_, H1_);
        transpose_h_kernel<<<dim3((H1_+31)/32, (H1_+31)/32),  tb>>>(W2, wT+WT_W2, H1_, H1_, H1_);
        transpose_h_kernel<<<dim3((OUT_+31)/32, (H1_+31)/32), tb>>>(Wo, wT+WT_WO, H1_, OUT_, H1_);
    }

    // dense head
    const dim3 grH((H1_ + 127) / 128, B_ / 128);
    const dim3 grO((OUT_ + 127) / 128, B_ / 128);
    hgemm<1, __half><<<grH, 256, DSMEM_H>>>(dec, DECS, wT + WT_MAP, DECS,
                                            t1, H1_, bmap, H1_, DECS);
    hgemm<2, __half><<<grH, 256, DSMEM_H>>>(t1, H1_, wT + WT_W1, H1_,
                                            t2, H1_, b1, H1_, H1_);
    hgemm<2, __half><<<grH, 256, DSMEM_H>>>(t2, H1_, wT + WT_W2, H1_,
                                            t1, H1_, b2, H1_, H1_);
    hgemm<0, float><<<grO, 256, DSMEM_H>>>(t1, H1_, wT + WT_WO, H1_,
                                           out, OUT_, bo, OUT_, H1_);
}